// round 15
// baseline (speedup 1.0000x reference)
#include <cuda_runtime.h>

// B = 65536 point clouds, N = 128 points, 3 coords.
// loss = mean( (xc @ R - yc)^2 )  with  R = U @ Vh  (SVD of C = xc^T yc)
//      = [ sum_b ( ||xc_b||^2 + ||yc_b||^2 - 2*nuclear_norm(C_b) ) ] / (B*N*3)
// nuclear_norm(C) = sum sqrt(eig(C^T C))  via closed-form 3x3 symmetric eigensolver.
//
// FINAL (R7 structure; best measured across 14 rounds): persistent CTAs
// (888 blocks, ~6/SM), grid-stride over 8192 groups of 8 batches, one warp
// per batch, smem transpose-reduce (no SHFL butterfly), double-buffered bsum
// so the warp-0 epilogue overlaps the other warps' next-iteration loads,
// one barrier per iteration, one global atomic per block. Runs at
// 5.8-6.0 TB/s — the measured achievable HBM read bandwidth for this stream
// (five independent structures all plateau here).

#define NB 65536
#define NPTS 128
#define WARPS_PER_BLOCK 8
#define THREADS (WARPS_PER_BLOCK * 32)
#define NGROUPS (NB / WARPS_PER_BLOCK)     // 8192 groups of 8 batches
#define GRID_P 888                          // ~6 resident blocks per SM

__device__ double g_accum = 0.0;
__device__ unsigned int g_count = 0u;

__global__ void __launch_bounds__(THREADS)
kabsch_fused(const float* __restrict__ x, const float* __restrict__ y,
             float* __restrict__ out) {
    const int tid  = threadIdx.x;
    const int lane = tid & 31;
    const int wib  = tid >> 5;

    // Warp-private reduction rows (36-float stride: 16B-aligned, conflict-free)
    __shared__ __align__(16) float red[WARPS_PER_BLOCK][17][36];
    // Double-buffered per-batch sums: epilogue(k) overlaps compute(k+1).
    __shared__ __align__(16) float bsum[2][WARPS_PER_BLOCK][20];

    float loss_acc = 0.0f;   // meaningful on lanes 0..7 of warp 0
    int buf = 0;

    for (int g = blockIdx.x; g < NGROUPS; g += GRID_P, buf ^= 1) {
        // group g = 8 batches; warp wib owns batch g*8+wib.
        const float4* xb = reinterpret_cast<const float4*>(x)
                         + (size_t)g * 768 + wib * 96;
        const float4* yb = reinterpret_cast<const float4*>(y)
                         + (size_t)g * 768 + wib * 96;

        float4 a0 = xb[3 * lane + 0];
        float4 a1 = xb[3 * lane + 1];
        float4 a2 = xb[3 * lane + 2];
        float4 b0 = yb[3 * lane + 0];
        float4 b1 = yb[3 * lane + 1];
        float4 b2 = yb[3 * lane + 2];

        float px[4][3] = {{a0.x, a0.y, a0.z}, {a0.w, a1.x, a1.y},
                          {a1.z, a1.w, a2.x}, {a2.y, a2.z, a2.w}};
        float py[4][3] = {{b0.x, b0.y, b0.z}, {b0.w, b1.x, b1.y},
                          {b1.z, b1.w, b2.x}, {b2.y, b2.z, b2.w}};

        // acc: [0..2]=sx, [3..5]=sy, [6]=sxx, [7]=syy, [8..16]=C row-major
        float acc[17];
#pragma unroll
        for (int i = 0; i < 17; i++) acc[i] = 0.0f;

#pragma unroll
        for (int p = 0; p < 4; p++) {
#pragma unroll
            for (int j = 0; j < 3; j++) {
                acc[j]     += px[p][j];
                acc[3 + j] += py[p][j];
                acc[6]     += px[p][j] * px[p][j];
                acc[7]     += py[p][j] * py[p][j];
            }
#pragma unroll
            for (int j = 0; j < 3; j++)
#pragma unroll
                for (int k = 0; k < 3; k++)
                    acc[8 + 3 * j + k] += px[p][j] * py[p][k];
        }

#pragma unroll
        for (int j = 0; j < 17; j++)
            red[wib][j][lane] = acc[j];      // warp-private: no block hazard
        __syncwarp();

        if (lane < 17) {
            const float4* row = reinterpret_cast<const float4*>(&red[wib][lane][0]);
            float4 v0 = row[0], v1 = row[1], v2 = row[2], v3 = row[3];
            float4 v4 = row[4], v5 = row[5], v6 = row[6], v7 = row[7];
            float s = (((v0.x + v0.y) + (v0.z + v0.w)) + ((v1.x + v1.y) + (v1.z + v1.w)))
                    + (((v2.x + v2.y) + (v2.z + v2.w)) + ((v3.x + v3.y) + (v3.z + v3.w)))
                    + (((v4.x + v4.y) + (v4.z + v4.w)) + ((v5.x + v5.y) + (v5.z + v5.w)))
                    + (((v6.x + v6.y) + (v6.z + v6.w)) + ((v7.x + v7.y) + (v7.z + v7.w)));
            bsum[buf][wib][lane] = s;
        }

        // One barrier per iteration: all warps' bsum[buf] visible to warp 0.
        // Warp 0 epilogues bsum[buf] while others run the next iteration
        // (they write bsum[buf^1] next; bsum[buf] is rewritten only after
        // the NEXT barrier, by which warp 0 has finished).
        __syncthreads();

        if (tid < 8) {
            const int b = tid;
            const float4* bp = reinterpret_cast<const float4*>(&bsum[buf][b][0]);
            float4 q0 = bp[0], q1 = bp[1], q2 = bp[2], q3 = bp[3];
            float c22 = bsum[buf][b][16];

            float sx0 = q0.x, sx1 = q0.y, sx2 = q0.z;
            float sy0 = q0.w, sy1 = q1.x, sy2 = q1.y;
            float sxx = q1.z, syy = q1.w;
            float C00 = q2.x, C01 = q2.y, C02 = q2.z;
            float C10 = q2.w, C11 = q3.x, C12 = q3.y;
            float C20 = q3.z, C21 = q3.w, C22 = c22;

            const float invN = 1.0f / (float)NPTS;

            float cc00 = C00 - sx0 * sy0 * invN;
            float cc01 = C01 - sx0 * sy1 * invN;
            float cc02 = C02 - sx0 * sy2 * invN;
            float cc10 = C10 - sx1 * sy0 * invN;
            float cc11 = C11 - sx1 * sy1 * invN;
            float cc12 = C12 - sx1 * sy2 * invN;
            float cc20 = C20 - sx2 * sy0 * invN;
            float cc21 = C21 - sx2 * sy1 * invN;
            float cc22 = C22 - sx2 * sy2 * invN;

            float ax = sxx - (sx0 * sx0 + sx1 * sx1 + sx2 * sx2) * invN;
            float ay = syy - (sy0 * sy0 + sy1 * sy1 + sy2 * sy2) * invN;

            // M = C^T C (symmetric PSD)
            float m00 = cc00 * cc00 + cc10 * cc10 + cc20 * cc20;
            float m11 = cc01 * cc01 + cc11 * cc11 + cc21 * cc21;
            float m22 = cc02 * cc02 + cc12 * cc12 + cc22 * cc22;
            float m01 = cc00 * cc01 + cc10 * cc11 + cc20 * cc21;
            float m02 = cc00 * cc02 + cc10 * cc12 + cc20 * cc22;
            float m12 = cc01 * cc02 + cc11 * cc12 + cc21 * cc22;

            // Closed-form eigenvalues (Smith's trig method)
            float q  = (m00 + m11 + m22) * (1.0f / 3.0f);
            float p1 = m01 * m01 + m02 * m02 + m12 * m12;
            float d0 = m00 - q, d1 = m11 - q, d2 = m22 - q;
            float p2 = d0 * d0 + d1 * d1 + d2 * d2 + 2.0f * p1;
            float p  = sqrtf(fmaxf(p2, 0.0f) * (1.0f / 6.0f));

            float nuclear;
            if (p < 1e-10f) {
                nuclear = 3.0f * sqrtf(fmaxf(q, 0.0f));
            } else {
                float ip  = 1.0f / p;
                float b00 = d0 * ip, b11 = d1 * ip, b22 = d2 * ip;
                float b01 = m01 * ip, b02 = m02 * ip, b12 = m12 * ip;
                float detB = b00 * (b11 * b22 - b12 * b12)
                           - b01 * (b01 * b22 - b12 * b02)
                           + b02 * (b01 * b12 - b11 * b02);
                float r = 0.5f * detB;
                r = fminf(1.0f, fmaxf(-1.0f, r));
                float phi = acosf(r) * (1.0f / 3.0f);
                float e1 = q + 2.0f * p * cosf(phi);
                float e3 = q + 2.0f * p * cosf(phi + 2.09439510239319549f);
                float e2 = 3.0f * q - e1 - e3;
                nuclear = sqrtf(fmaxf(e1, 0.0f))
                        + sqrtf(fmaxf(e2, 0.0f))
                        + sqrtf(fmaxf(e3, 0.0f));
            }

            loss_acc += ax + ay - 2.0f * nuclear;
        }
    }

    // ---- block finalize: one atomic per block ----
    if (tid < 8) {
        float loss = loss_acc;
        loss += __shfl_xor_sync(0xFFu, loss, 4);
        loss += __shfl_xor_sync(0xFFu, loss, 2);
        loss += __shfl_xor_sync(0xFFu, loss, 1);

        if (tid == 0) {
            atomicAdd(&g_accum, (double)loss);

            // Last-block finalize: counter wraps at GRID_P-1, so g_count and
            // g_accum are clean for the next graph replay.
            __threadfence();
            unsigned int prev = atomicInc(&g_count, GRID_P - 1u);
            if (prev == GRID_P - 1u) {
                double total = atomicAdd(&g_accum, 0.0);  // coherent read
                const double scale = 1.0 / ((double)NB * (double)NPTS * 3.0);
                out[0] = (float)(total * scale);
                g_accum = 0.0;                            // reset for replay
            }
        }
    }
}

extern "C" void kernel_launch(void* const* d_in, const int* in_sizes, int n_in,
                              void* d_out, int out_size) {
    const float* x = (const float*)d_in[0];
    const float* y = (const float*)d_in[1];
    float* out = (float*)d_out;

    kabsch_fused<<<GRID_P, THREADS>>>(x, y, out);
}

// round 16
// speedup vs baseline: 1.0365x; 1.0365x over previous
#include <cuda_runtime.h>

// B = 65536 point clouds, N = 128 points, 3 coords.
// loss = mean( (xc @ R - yc)^2 )  with  R = U @ Vh  (SVD of C = xc^T yc)
//      = [ sum_b ( ||xc_b||^2 + ||yc_b||^2 - 2*nuclear_norm(C_b) ) ] / (B*N*3)
// nuclear_norm(C) = sum sqrt(eig(C^T C))  via closed-form 3x3 symmetric eigensolver.
//
// FINAL (best measured across 15 rounds): persistent CTAs (888 blocks,
// 6/SM — register-file ceiling at 40 regs), grid-stride over 8192 groups of
// 8 batches, one warp per batch, smem transpose-reduce, double-buffered
// bsum so the warp-0 epilogue overlaps the other warps' next-iteration
// loads, one barrier per iteration, one global atomic per block.
// Runs at 5.8-6.0 TB/s = the measured achievable HBM read bandwidth for
// this stream (five independent memory-path structures all plateau here);
// kernel time ~95% of the pure-stream floor at that bandwidth.

#define NB 65536
#define NPTS 128
#define WARPS_PER_BLOCK 8
#define THREADS (WARPS_PER_BLOCK * 32)
#define NGROUPS (NB / WARPS_PER_BLOCK)     // 8192 groups of 8 batches
#define GRID_P 888                          // 6 resident blocks per SM

__device__ double g_accum = 0.0;
__device__ unsigned int g_count = 0u;

__global__ void __launch_bounds__(THREADS)
kabsch_fused(const float* __restrict__ x, const float* __restrict__ y,
             float* __restrict__ out) {
    const int tid  = threadIdx.x;
    const int lane = tid & 31;
    const int wib  = tid >> 5;

    // Warp-private reduction rows (36-float stride: 16B-aligned, conflict-free)
    __shared__ __align__(16) float red[WARPS_PER_BLOCK][17][36];
    // Double-buffered per-batch sums: epilogue(k) overlaps compute(k+1).
    __shared__ __align__(16) float bsum[2][WARPS_PER_BLOCK][20];

    float loss_acc = 0.0f;   // meaningful on lanes 0..7 of warp 0
    int buf = 0;

    for (int g = blockIdx.x; g < NGROUPS; g += GRID_P, buf ^= 1) {
        // group g = 8 batches; warp wib owns batch g*8+wib.
        const float4* xb = reinterpret_cast<const float4*>(x)
                         + (size_t)g * 768 + wib * 96;
        const float4* yb = reinterpret_cast<const float4*>(y)
                         + (size_t)g * 768 + wib * 96;

        float4 a0 = xb[3 * lane + 0];
        float4 a1 = xb[3 * lane + 1];
        float4 a2 = xb[3 * lane + 2];
        float4 b0 = yb[3 * lane + 0];
        float4 b1 = yb[3 * lane + 1];
        float4 b2 = yb[3 * lane + 2];

        float px[4][3] = {{a0.x, a0.y, a0.z}, {a0.w, a1.x, a1.y},
                          {a1.z, a1.w, a2.x}, {a2.y, a2.z, a2.w}};
        float py[4][3] = {{b0.x, b0.y, b0.z}, {b0.w, b1.x, b1.y},
                          {b1.z, b1.w, b2.x}, {b2.y, b2.z, b2.w}};

        // acc: [0..2]=sx, [3..5]=sy, [6]=sxx, [7]=syy, [8..16]=C row-major
        float acc[17];
#pragma unroll
        for (int i = 0; i < 17; i++) acc[i] = 0.0f;

#pragma unroll
        for (int p = 0; p < 4; p++) {
#pragma unroll
            for (int j = 0; j < 3; j++) {
                acc[j]     += px[p][j];
                acc[3 + j] += py[p][j];
                acc[6]     += px[p][j] * px[p][j];
                acc[7]     += py[p][j] * py[p][j];
            }
#pragma unroll
            for (int j = 0; j < 3; j++)
#pragma unroll
                for (int k = 0; k < 3; k++)
                    acc[8 + 3 * j + k] += px[p][j] * py[p][k];
        }

#pragma unroll
        for (int j = 0; j < 17; j++)
            red[wib][j][lane] = acc[j];      // warp-private: no block hazard
        __syncwarp();

        if (lane < 17) {
            const float4* row = reinterpret_cast<const float4*>(&red[wib][lane][0]);
            float4 v0 = row[0], v1 = row[1], v2 = row[2], v3 = row[3];
            float4 v4 = row[4], v5 = row[5], v6 = row[6], v7 = row[7];
            float s = (((v0.x + v0.y) + (v0.z + v0.w)) + ((v1.x + v1.y) + (v1.z + v1.w)))
                    + (((v2.x + v2.y) + (v2.z + v2.w)) + ((v3.x + v3.y) + (v3.z + v3.w)))
                    + (((v4.x + v4.y) + (v4.z + v4.w)) + ((v5.x + v5.y) + (v5.z + v5.w)))
                    + (((v6.x + v6.y) + (v6.z + v6.w)) + ((v7.x + v7.y) + (v7.z + v7.w)));
            bsum[buf][wib][lane] = s;
        }

        // One barrier per iteration: all warps' bsum[buf] visible to warp 0.
        // Warp 0 epilogues bsum[buf] while others run the next iteration
        // (they write bsum[buf^1] next; bsum[buf] is rewritten only after
        // the NEXT barrier, by which warp 0 has finished).
        __syncthreads();

        if (tid < 8) {
            const int b = tid;
            const float4* bp = reinterpret_cast<const float4*>(&bsum[buf][b][0]);
            float4 q0 = bp[0], q1 = bp[1], q2 = bp[2], q3 = bp[3];
            float c22 = bsum[buf][b][16];

            float sx0 = q0.x, sx1 = q0.y, sx2 = q0.z;
            float sy0 = q0.w, sy1 = q1.x, sy2 = q1.y;
            float sxx = q1.z, syy = q1.w;
            float C00 = q2.x, C01 = q2.y, C02 = q2.z;
            float C10 = q2.w, C11 = q3.x, C12 = q3.y;
            float C20 = q3.z, C21 = q3.w, C22 = c22;

            const float invN = 1.0f / (float)NPTS;

            float cc00 = C00 - sx0 * sy0 * invN;
            float cc01 = C01 - sx0 * sy1 * invN;
            float cc02 = C02 - sx0 * sy2 * invN;
            float cc10 = C10 - sx1 * sy0 * invN;
            float cc11 = C11 - sx1 * sy1 * invN;
            float cc12 = C12 - sx1 * sy2 * invN;
            float cc20 = C20 - sx2 * sy0 * invN;
            float cc21 = C21 - sx2 * sy1 * invN;
            float cc22 = C22 - sx2 * sy2 * invN;

            float ax = sxx - (sx0 * sx0 + sx1 * sx1 + sx2 * sx2) * invN;
            float ay = syy - (sy0 * sy0 + sy1 * sy1 + sy2 * sy2) * invN;

            // M = C^T C (symmetric PSD)
            float m00 = cc00 * cc00 + cc10 * cc10 + cc20 * cc20;
            float m11 = cc01 * cc01 + cc11 * cc11 + cc21 * cc21;
            float m22 = cc02 * cc02 + cc12 * cc12 + cc22 * cc22;
            float m01 = cc00 * cc01 + cc10 * cc11 + cc20 * cc21;
            float m02 = cc00 * cc02 + cc10 * cc12 + cc20 * cc22;
            float m12 = cc01 * cc02 + cc11 * cc12 + cc21 * cc22;

            // Closed-form eigenvalues (Smith's trig method)
            float q  = (m00 + m11 + m22) * (1.0f / 3.0f);
            float p1 = m01 * m01 + m02 * m02 + m12 * m12;
            float d0 = m00 - q, d1 = m11 - q, d2 = m22 - q;
            float p2 = d0 * d0 + d1 * d1 + d2 * d2 + 2.0f * p1;
            float p  = sqrtf(fmaxf(p2, 0.0f) * (1.0f / 6.0f));

            float nuclear;
            if (p < 1e-10f) {
                nuclear = 3.0f * sqrtf(fmaxf(q, 0.0f));
            } else {
                float ip  = 1.0f / p;
                float b00 = d0 * ip, b11 = d1 * ip, b22 = d2 * ip;
                float b01 = m01 * ip, b02 = m02 * ip, b12 = m12 * ip;
                float detB = b00 * (b11 * b22 - b12 * b12)
                           - b01 * (b01 * b22 - b12 * b02)
                           + b02 * (b01 * b12 - b11 * b02);
                float r = 0.5f * detB;
                r = fminf(1.0f, fmaxf(-1.0f, r));
                float phi = acosf(r) * (1.0f / 3.0f);
                float e1 = q + 2.0f * p * cosf(phi);
                float e3 = q + 2.0f * p * cosf(phi + 2.09439510239319549f);
                float e2 = 3.0f * q - e1 - e3;
                nuclear = sqrtf(fmaxf(e1, 0.0f))
                        + sqrtf(fmaxf(e2, 0.0f))
                        + sqrtf(fmaxf(e3, 0.0f));
            }

            loss_acc += ax + ay - 2.0f * nuclear;
        }
    }

    // ---- block finalize: one atomic per block ----
    if (tid < 8) {
        float loss = loss_acc;
        loss += __shfl_xor_sync(0xFFu, loss, 4);
        loss += __shfl_xor_sync(0xFFu, loss, 2);
        loss += __shfl_xor_sync(0xFFu, loss, 1);

        if (tid == 0) {
            atomicAdd(&g_accum, (double)loss);

            // Last-block finalize: counter wraps at GRID_P-1, so g_count and
            // g_accum are clean for the next graph replay.
            __threadfence();
            unsigned int prev = atomicInc(&g_count, GRID_P - 1u);
            if (prev == GRID_P - 1u) {
                double total = atomicAdd(&g_accum, 0.0);  // coherent read
                const double scale = 1.0 / ((double)NB * (double)NPTS * 3.0);
                out[0] = (float)(total * scale);
                g_accum = 0.0;                            // reset for replay
            }
        }
    }
}

extern "C" void kernel_launch(void* const* d_in, const int* in_sizes, int n_in,
                              void* d_out, int out_size) {
    const float* x = (const float*)d_in[0];
    const float* y = (const float*)d_in[1];
    float* out = (float*)d_out;

    kabsch_fused<<<GRID_P, THREADS>>>(x, y, out);
}